// round 16
// baseline (speedup 1.0000x reference)
#include <cuda_runtime.h>
#include <cuda_fp16.h>
#include <math.h>
#include <stdint.h>

#define B_  2
#define T_  4096
#define D_  1024
#define H_  8
#define HD_ 128
#define L_  5
#define M_  (B_*T_)   /* 8192 */

// fp16 projected Q/K/V (attention inputs; GEMM writes fp16 directly)
__device__ __half g_q[(size_t)M_ * D_];
__device__ __half g_k[(size_t)M_ * D_];
__device__ __half g_v[(size_t)M_ * D_];

// fp16 copies of GEMM inputs
__device__ __half g_qh[(size_t)M_ * D_];
__device__ __half g_kh[(size_t)M_ * D_];
__device__ __half g_vh[(size_t)M_ * D_];
__device__ __half g_wqh[(size_t)D_ * D_];
__device__ __half g_wkh[(size_t)D_ * D_];
__device__ __half g_wvh[(size_t)D_ * D_];

// ===========================================================================
// PTX helpers (baseline PTX only — sm_103 base target, no 'a' features)
// ===========================================================================
__device__ __forceinline__ uint32_t smem_u32(const void* p) {
    uint32_t a;
    asm("{ .reg .u64 t; cvta.to.shared.u64 t, %1; cvt.u32.u64 %0, t; }"
        : "=r"(a) : "l"(p));
    return a;
}

__device__ __forceinline__ void cp_async16(uint32_t s, const void* g) {
    asm volatile("cp.async.cg.shared.global [%0], [%1], 16;\n"
                 :: "r"(s), "l"(g) : "memory");
}
#define CP_COMMIT()  asm volatile("cp.async.commit_group;" ::: "memory")
#define CP_WAIT(n)   asm volatile("cp.async.wait_group %0;" :: "n"(n) : "memory")

// XOR swizzle, 16B granularity, within 128B rows
#define SWZ128(o) ((o) ^ (((o) >> 3) & 0x70))

__device__ __forceinline__ void ldsm_x4(uint32_t& r0, uint32_t& r1,
                                        uint32_t& r2, uint32_t& r3, uint32_t a) {
    asm volatile("ldmatrix.sync.aligned.m8n8.x4.shared.b16 {%0,%1,%2,%3}, [%4];"
                 : "=r"(r0), "=r"(r1), "=r"(r2), "=r"(r3) : "r"(a));
}

__device__ __forceinline__ void mma_f16(float& c0, float& c1, float& c2, float& c3,
                                        uint32_t a0, uint32_t a1, uint32_t a2, uint32_t a3,
                                        uint32_t b0, uint32_t b1) {
    asm volatile(
        "mma.sync.aligned.m16n8k16.row.col.f32.f16.f16.f32 "
        "{%0,%1,%2,%3}, {%4,%5,%6,%7}, {%8,%9}, {%0,%1,%2,%3};"
        : "+f"(c0), "+f"(c1), "+f"(c2), "+f"(c3)
        : "r"(a0), "r"(a1), "r"(a2), "r"(a3), "r"(b0), "r"(b1));
}

__device__ __forceinline__ uint32_t h2_bits(__half2 h) {
    union { __half2 h; uint32_t u; } cvt;
    cvt.h = h;
    return cvt.u;
}

// load 4 consecutive halves -> float4 (8B load)
__device__ __forceinline__ float4 ldh4(const __half* p) {
    const uint2 u = *(const uint2*)p;
    union { uint32_t u; __half2 h; } a, b;
    a.u = u.x; b.u = u.y;
    const float2 fa = __half22float2(a.h);
    const float2 fb = __half22float2(b.h);
    return make_float4(fa.x, fa.y, fb.x, fb.y);
}

// ===========================================================================
// fp32 -> fp16 conversion of ONE X tensor + ONE W matrix (4 float4/thread).
// Launched per projection so conversions can overlap GEMMs on other streams.
// ===========================================================================
#define XN4 ((M_ * D_) / 4)   /* 2097152 */
#define WN4 ((D_ * D_) / 4)   /*  262144 */
#define XQ_  (XN4 / 4)        /*  524288 */
#define WQ_  (WN4 / 4)        /*   65536 */
#define CVT_PAIR_QUADS (XQ_ + WQ_)
#define CVT_PAIR_GRID  ((CVT_PAIR_QUADS + 255) / 256)

__global__ __launch_bounds__(256)
void cvt_pair_kernel(const float4* __restrict__ x, const float4* __restrict__ w,
                     __half* __restrict__ xh, __half* __restrict__ wh)
{
    const int qi = blockIdx.x * blockDim.x + threadIdx.x;
    if (qi >= CVT_PAIR_QUADS) return;

    const float4* src;
    uint32_t* dstw;
    int off;
    if (qi < XQ_) { off = qi * 4;          src = x; dstw = (uint32_t*)xh; }
    else          { off = (qi - XQ_) * 4;  src = w; dstw = (uint32_t*)wh; }

    const float4 v0 = src[off];
    const float4 v1 = src[off + 1];
    const float4 v2 = src[off + 2];
    const float4 v3 = src[off + 3];
    uint4 o0, o1;
    o0.x = h2_bits(__floats2half2_rn(v0.x, v0.y));
    o0.y = h2_bits(__floats2half2_rn(v0.z, v0.w));
    o0.z = h2_bits(__floats2half2_rn(v1.x, v1.y));
    o0.w = h2_bits(__floats2half2_rn(v1.z, v1.w));
    o1.x = h2_bits(__floats2half2_rn(v2.x, v2.y));
    o1.y = h2_bits(__floats2half2_rn(v2.z, v2.w));
    o1.z = h2_bits(__floats2half2_rn(v3.x, v3.y));
    o1.w = h2_bits(__floats2half2_rn(v3.z, v3.w));
    *(uint4*)(dstw + off * 2)     = o0;
    *(uint4*)(dstw + off * 2 + 4) = o1;
}

// ===========================================================================
// Fused fp16 GEMM:  C[M,N] = X[M,K] @ W^T + bias  (blockIdx.z selects slot)
// CTA tile 256x128, BK=64 halves, 512 threads / 16 warps (4m x 4n),
// warp tile 64x32. 3-stage cp.async pipeline (144 KB smem), ONE
// __syncthreads per iteration. skip_z: z index whose bx==7 tile is dead
// (k head 7 is never read by attention).
// ===========================================================================
#define BKC     64
#define NITER   (D_ / BKC)               /* 16 */
#define BM_     256
#define A_TILE  (BM_ * 128)              /* 32 KB */
#define B_TILE  (128 * 128)              /* 16 KB */
#define STAGE_B (A_TILE + B_TILE)        /* 48 KB */
#define NSTAGE  3
#define SMEM_SZ (NSTAGE * STAGE_B)       /* 144 KB */

__global__ __launch_bounds__(512)
void gemm_f16_fused(const __half* __restrict__ X0, const __half* __restrict__ W0,
                    const float* __restrict__ b0, __half* __restrict__ C0,
                    const __half* __restrict__ X1, const __half* __restrict__ W1,
                    const float* __restrict__ b1, __half* __restrict__ C1,
                    int skip_z)
{
    const int z = blockIdx.z;
    const int bx = blockIdx.x;
    if (z == skip_z && bx == 7) return;

    const __half* X    = (z == 0) ? X0 : X1;
    const __half* W    = (z == 0) ? W0 : W1;
    const float*  bias = (z == 0) ? b0 : b1;
    __half*       C    = (z == 0) ? C0 : C1;

    extern __shared__ char smem[];
    const uint32_t sbase = smem_u32(smem);
    const int tid  = threadIdx.x;
    const int wid  = tid >> 5;
    const int lane = tid & 31;
    const int wm   = wid >> 2;          // 0..3  (64-row band)
    const int wn   = wid & 3;           // 0..3  (32-col band)

    const int bm = blockIdx.y * BM_;
    const int bn = bx * 128;
    const int K  = D_;

    float acc[4][4][4];
#pragma unroll
    for (int i = 0; i < 4; i++)
#pragma unroll
        for (int j = 0; j < 4; j++)
#pragma unroll
            for (int r = 0; r < 4; r++) acc[i][j][r] = 0.0f;

    auto load_stage = [&](int s, int k0) {
        const uint32_t sa = sbase + s * STAGE_B;
        const uint32_t sb = sa + A_TILE;
        const __half* Ab = X + (size_t)bm * K + k0 * BKC;
        const __half* Bb = W + (size_t)bn * K + k0 * BKC;
#pragma unroll
        for (int i = 0; i < 4; i++) {
            const int c   = i * 512 + tid;     // 0..2047
            const int row = c >> 3;
            const int c16 = c & 7;
            const uint32_t off = SWZ128((uint32_t)(row * 128 + c16 * 16));
            cp_async16(sa + off, Ab + (size_t)row * K + c16 * 8);
        }
#pragma unroll
        for (int i = 0; i < 2; i++) {
            const int c   = i * 512 + tid;     // 0..1023
            const int row = c >> 3;
            const int c16 = c & 7;
            const uint32_t off = SWZ128((uint32_t)(row * 128 + c16 * 16));
            cp_async16(sb + off, Bb + (size_t)row * K + c16 * 8);
        }
        CP_COMMIT();
    };

    load_stage(0, 0);
    load_stage(1, 1);

    const int a_row = wm * 64 + (lane & 15);
    const int a_byt = (lane >> 4) << 4;
    const int b_row = wn * 32 + ((lane >> 4) << 3) + (lane & 7);
    const int b_byt = ((lane >> 3) & 1) << 4;

    int cur = 0;
    for (int k0 = 0; k0 < NITER; k0++) {
        if (k0 < NITER - 1) { CP_WAIT(1); }
        else                { CP_WAIT(0); }
        __syncthreads();   // data visible + WAR on the slot issued below

        if (k0 + 2 < NITER)
            load_stage((cur + 2) % NSTAGE, k0 + 2);

        const uint32_t sa = sbase + cur * STAGE_B;
        const uint32_t sb = sa + A_TILE;

#pragma unroll
        for (int kk = 0; kk < 4; kk++) {
            const int kbyte = kk * 32;

            uint32_t af[4][4];
#pragma unroll
            for (int i = 0; i < 4; i++) {
                const uint32_t ad = sa + SWZ128((uint32_t)((a_row + i * 16) * 128
                                                           + kbyte + a_byt));
                ldsm_x4(af[i][0], af[i][1], af[i][2], af[i][3], ad);
            }
            uint32_t bf[4][2];
#pragma unroll
            for (int j2 = 0; j2 < 2; j2++) {
                const uint32_t bd = sb + SWZ128((uint32_t)((b_row + j2 * 16) * 128
                                                           + kbyte + b_byt));
                uint32_t r0, r1, r2, r3;
                ldsm_x4(r0, r1, r2, r3, bd);
                bf[j2 * 2][0] = r0; bf[j2 * 2][1] = r1;
                bf[j2 * 2 + 1][0] = r2; bf[j2 * 2 + 1][1] = r3;
            }
#pragma unroll
            for (int i = 0; i < 4; i++)
#pragma unroll
                for (int j = 0; j < 4; j++)
                    mma_f16(acc[i][j][0], acc[i][j][1], acc[i][j][2], acc[i][j][3],
                            af[i][0], af[i][1], af[i][2], af[i][3],
                            bf[j][0], bf[j][1]);
        }
        cur = (cur + 1) % NSTAGE;
    }

    // epilogue: fp32 acc + bias -> __half2 stores
    const int lr = lane >> 2;
    const int lc = lane & 3;
#pragma unroll
    for (int i = 0; i < 4; i++) {
        const int row0 = bm + wm * 64 + i * 16 + lr;
#pragma unroll
        for (int j = 0; j < 4; j++) {
            const int col0 = bn + wn * 32 + j * 8 + lc * 2;
            const float bb0 = bias[col0], bb1 = bias[col0 + 1];
            const __half2 v0 = __floats2half2_rn(acc[i][j][0] + bb0, acc[i][j][1] + bb1);
            const __half2 v1 = __floats2half2_rn(acc[i][j][2] + bb0, acc[i][j][3] + bb1);
            *(__half2*)&C[(size_t)row0 * D_ + col0] = v0;
            *(__half2*)&C[(size_t)(row0 + 8) * D_ + col0] = v1;
        }
    }
}

// ---------------------------------------------------------------------------
// Attention: one warp per PAIR (ta, tb = ta + dil) of one (b, h).
// fp16 q/k/v loads (8B per lane), fp32 math. Lane l -> dims [4l, 4l+4).
// ---------------------------------------------------------------------------
__global__ __launch_bounds__(256)
void attn_kernel(const float* __restrict__ Er, const int* __restrict__ layer_p,
                 float* __restrict__ out, int write_attn)
{
    const int gwarp = (blockIdx.x * blockDim.x + threadIdx.x) >> 5;
    const int lane  = threadIdx.x & 31;
    const int npair = T_ / 2;
    if (gwarp >= B_ * H_ * npair) return;

    const int p = gwarp % npair;
    const int h = (gwarp / npair) % H_;
    const int b = gwarp / (npair * H_);

    const int layer = layer_p ? *layer_p : 1;
    const int dil = 1 << layer;
    const int pad = dil * (L_ / 2);
    const int Tp  = T_ + 2 * pad;

    const int g  = p / dil, r = p % dil;
    const int ta = g * 2 * dil + r;
    const int tb = ta + dil;
    const bool has_b = (tb < T_);

    const int srck[H_]   = {0, 1, 2, 3, 4, 5, 6, 6};
    const int shifts[H_] = {0, 0, 0, 0, -2, -1, 1, 2};
    const int sh = shifts[h];
    const int kcol = srck[h] * HD_;
    const int hcol = h * HD_;

    const size_t rowa = (size_t)(b * T_ + ta) * D_;
    const size_t rowb = (size_t)(b * T_ + tb) * D_;
    const float4 qa = ldh4(g_q + rowa + hcol + lane * 4);
    const float4 qb = has_b ? ldh4(g_q + rowb + hcol + lane * 4)
                            : make_float4(0.f, 0.f, 0.f, 0.f);

    float er[4][L_];
    const float* erp = Er + ((size_t)h * HD_ + lane * 4) * L_;
#pragma unroll
    for (int d = 0; d < 4; d++)
#pragma unroll
        for (int j = 0; j < L_; j++) er[d][j] = erp[d * L_ + j];

    int  tt[L_ + 1];
    bool val[L_ + 1];
    float dka[L_], dkb[L_];
#pragma unroll
    for (int i = 0; i < L_ + 1; i++) {
        int pi = ta + (sh + i) * dil;
        pi %= Tp; if (pi < 0) pi += Tp;
        const bool v = (pi >= pad) && (pi < pad + T_);
        val[i] = v;
        tt[i] = pi - pad;

        float4 k4 = make_float4(0.f, 0.f, 0.f, 0.f);
        if (v)
            k4 = ldh4(g_k + (size_t)(b * T_ + tt[i]) * D_ + kcol + lane * 4);
        if (i < L_)
            dka[i] = qa.x * k4.x + qa.y * k4.y + qa.z * k4.z + qa.w * k4.w;
        if (i > 0)
            dkb[i - 1] = qb.x * k4.x + qb.y * k4.y + qb.z * k4.z + qb.w * k4.w;
    }

    float sa[L_], sb[L_];
#pragma unroll
    for (int j = 0; j < L_; j++) {
        float ra = dka[j] + qa.x * er[0][j] + qa.y * er[1][j]
                          + qa.z * er[2][j] + qa.w * er[3][j];
        float rb = dkb[j] + qb.x * er[0][j] + qb.y * er[1][j]
                          + qb.z * er[2][j] + qb.w * er[3][j];
#pragma unroll
        for (int o = 16; o > 0; o >>= 1) {
            ra += __shfl_xor_sync(0xffffffffu, ra, o);
            rb += __shfl_xor_sync(0xffffffffu, rb, o);
        }
        sa[j] = val[j]     ? (ra * 0.08838834764831845f) : -INFINITY;
        sb[j] = val[j + 1] ? (rb * 0.08838834764831845f) : -INFINITY;
    }

    float mxa = sa[0], mxb = sb[0];
#pragma unroll
    for (int j = 1; j < L_; j++) { mxa = fmaxf(mxa, sa[j]); mxb = fmaxf(mxb, sb[j]); }
    float suma = 0.f, sumb = 0.f, wa[L_], wb[L_];
#pragma unroll
    for (int j = 0; j < L_; j++) {
        wa[j] = expf(sa[j] - mxa); suma += wa[j];
        wb[j] = expf(sb[j] - mxb); sumb += wb[j];
    }
    const float inva = 1.0f / suma;
    const float invb = 1.0f / sumb;

    float4 oa = make_float4(0.f, 0.f, 0.f, 0.f);
    float4 ob = make_float4(0.f, 0.f, 0.f, 0.f);
#pragma unroll
    for (int i = 0; i < L_ + 1; i++) {
        if (val[i]) {
            const float4 v4 = ldh4(g_v + (size_t)(b * T_ + tt[i]) * D_
                                   + hcol + lane * 4);
            if (i < L_) {
                const float a = wa[i] * inva;
                oa.x = fmaf(a, v4.x, oa.x); oa.y = fmaf(a, v4.y, oa.y);
                oa.z = fmaf(a, v4.z, oa.z); oa.w = fmaf(a, v4.w, oa.w);
            }
            if (i > 0) {
                const float a = wb[i - 1] * invb;
                ob.x = fmaf(a, v4.x, ob.x); ob.y = fmaf(a, v4.y, ob.y);
                ob.z = fmaf(a, v4.z, ob.z); ob.w = fmaf(a, v4.w, ob.w);
            }
        }
    }

    *(float4*)(out + rowa + hcol + lane * 4) = oa;
    if (has_b)
        *(float4*)(out + rowb + hcol + lane * 4) = ob;

    if (write_attn && lane < L_) {
        const size_t base = (size_t)M_ * D_;
        out[base + (((size_t)(b * H_ + h)) * T_ + ta) * L_ + lane] = wa[lane] * inva;
        if (has_b)
            out[base + (((size_t)(b * H_ + h)) * T_ + tb) * L_ + lane] = wb[lane] * invb;
    }
}

extern "C" void kernel_launch(void* const* d_in, const int* in_sizes, int n_in,
                              void* d_out, int out_size)
{
    const float* query = (const float*)d_in[0];
    const float* key   = (const float*)d_in[1];
    const float* value = (const float*)d_in[2];
    const float* Wq    = (const float*)d_in[3];
    const float* bq    = (const float*)d_in[4];
    const float* Wk    = (const float*)d_in[5];
    const float* bk    = (const float*)d_in[6];
    const float* Wv    = (const float*)d_in[7];
    const float* bv    = (const float*)d_in[8];
    const float* Er    = (const float*)d_in[9];
    const int*   layer = (n_in > 10) ? (const int*)d_in[10] : nullptr;

    __half *qo, *ko, *vo;
    cudaGetSymbolAddress((void**)&qo, g_q);
    cudaGetSymbolAddress((void**)&ko, g_k);
    cudaGetSymbolAddress((void**)&vo, g_v);
    __half *qh, *kh, *vh, *wqh, *wkh, *wvh;
    cudaGetSymbolAddress((void**)&qh, g_qh);
    cudaGetSymbolAddress((void**)&kh, g_kh);
    cudaGetSymbolAddress((void**)&vh, g_vh);
    cudaGetSymbolAddress((void**)&wqh, g_wqh);
    cudaGetSymbolAddress((void**)&wkh, g_wkh);
    cudaGetSymbolAddress((void**)&wvh, g_wvh);

    // Lazy one-time stream/event setup (no device memory involved). Created
    // on the uncaptured correctness call; reused (as graph fork/join edges)
    // during capture. s1 MUST be non-blocking to avoid legacy-stream
    // serialization.
    static cudaStream_t s1 = nullptr;
    static cudaEvent_t evRoot = nullptr, evQ = nullptr;
    if (!s1) {
        cudaStreamCreateWithFlags(&s1, cudaStreamNonBlocking);
        cudaEventCreateWithFlags(&evRoot, cudaEventDisableTiming);
        cudaEventCreateWithFlags(&evQ, cudaEventDisableTiming);
    }

    cudaFuncSetAttribute(gemm_f16_fused,
                         cudaFuncAttributeMaxDynamicSharedMemorySize, SMEM_SZ);

    // fork: s1 branches off the capture (legacy) stream
    cudaEventRecord(evRoot, 0);
    cudaStreamWaitEvent(s1, evRoot, 0);

    // S1 branch: cvt Q -> GEMM Q
    cvt_pair_kernel<<<CVT_PAIR_GRID, 256, 0, s1>>>((const float4*)query,
                                                   (const float4*)Wq, qh, wqh);
    {
        dim3 gq(D_ / 128, M_ / BM_, 1);
        gemm_f16_fused<<<gq, 512, SMEM_SZ, s1>>>(qh, wqh, bq, qo,
                                                 qh, wqh, bq, qo, /*skip_z=*/-1);
    }
    cudaEventRecord(evQ, s1);

    // S0 branch: cvt K, cvt V -> GEMM K+V (z=0 is K: skip dead head-7 tile)
    cvt_pair_kernel<<<CVT_PAIR_GRID, 256>>>((const float4*)key,
                                            (const float4*)Wk, kh, wkh);
    cvt_pair_kernel<<<CVT_PAIR_GRID, 256>>>((const float4*)value,
                                            (const float4*)Wv, vh, wvh);
    {
        dim3 gkv(D_ / 128, M_ / BM_, 2);
        gemm_f16_fused<<<gkv, 512, SMEM_SZ>>>(kh, wkh, bk, ko,
                                              vh, wvh, bv, vo, /*skip_z=*/0);
    }

    // join: attention needs Q too
    cudaStreamWaitEvent(0, evQ, 0);

    const int write_attn = (out_size > M_ * D_) ? 1 : 0;
    const int total_warps = B_ * H_ * (T_ / 2);
    attn_kernel<<<(total_warps * 32) / 256, 256>>>(Er, layer, (float*)d_out, write_attn);
}

// round 17
// speedup vs baseline: 1.1072x; 1.1072x over previous
#include <cuda_runtime.h>
#include <cuda_fp16.h>
#include <math.h>
#include <stdint.h>

#define B_  2
#define T_  4096
#define D_  1024
#define H_  8
#define HD_ 128
#define L_  5
#define M_  (B_*T_)   /* 8192 */

// fp16 projected Q/K/V (attention inputs; GEMM writes fp16 directly)
__device__ __half g_q[(size_t)M_ * D_];
__device__ __half g_k[(size_t)M_ * D_];
__device__ __half g_v[(size_t)M_ * D_];

// fp16 copies of GEMM inputs
__device__ __half g_qh[(size_t)M_ * D_];
__device__ __half g_kh[(size_t)M_ * D_];
__device__ __half g_vh[(size_t)M_ * D_];
__device__ __half g_wqh[(size_t)D_ * D_];
__device__ __half g_wkh[(size_t)D_ * D_];
__device__ __half g_wvh[(size_t)D_ * D_];

// ===========================================================================
// PTX helpers (baseline PTX only — sm_103 base target, no 'a' features)
// ===========================================================================
__device__ __forceinline__ uint32_t smem_u32(const void* p) {
    uint32_t a;
    asm("{ .reg .u64 t; cvta.to.shared.u64 t, %1; cvt.u32.u64 %0, t; }"
        : "=r"(a) : "l"(p));
    return a;
}

__device__ __forceinline__ void cp_async16(uint32_t s, const void* g) {
    asm volatile("cp.async.cg.shared.global [%0], [%1], 16;\n"
                 :: "r"(s), "l"(g) : "memory");
}
#define CP_COMMIT()  asm volatile("cp.async.commit_group;" ::: "memory")
#define CP_WAIT(n)   asm volatile("cp.async.wait_group %0;" :: "n"(n) : "memory")

// XOR swizzle, 16B granularity, within 128B rows
#define SWZ128(o) ((o) ^ (((o) >> 3) & 0x70))

__device__ __forceinline__ void ldsm_x4(uint32_t& r0, uint32_t& r1,
                                        uint32_t& r2, uint32_t& r3, uint32_t a) {
    asm volatile("ldmatrix.sync.aligned.m8n8.x4.shared.b16 {%0,%1,%2,%3}, [%4];"
                 : "=r"(r0), "=r"(r1), "=r"(r2), "=r"(r3) : "r"(a));
}

__device__ __forceinline__ void mma_f16(float& c0, float& c1, float& c2, float& c3,
                                        uint32_t a0, uint32_t a1, uint32_t a2, uint32_t a3,
                                        uint32_t b0, uint32_t b1) {
    asm volatile(
        "mma.sync.aligned.m16n8k16.row.col.f32.f16.f16.f32 "
        "{%0,%1,%2,%3}, {%4,%5,%6,%7}, {%8,%9}, {%0,%1,%2,%3};"
        : "+f"(c0), "+f"(c1), "+f"(c2), "+f"(c3)
        : "r"(a0), "r"(a1), "r"(a2), "r"(a3), "r"(b0), "r"(b1));
}

__device__ __forceinline__ uint32_t h2_bits(__half2 h) {
    union { __half2 h; uint32_t u; } cvt;
    cvt.h = h;
    return cvt.u;
}

// load 4 consecutive halves -> float4 (8B load)
__device__ __forceinline__ float4 ldh4(const __half* p) {
    const uint2 u = *(const uint2*)p;
    union { uint32_t u; __half2 h; } a, b;
    a.u = u.x; b.u = u.y;
    const float2 fa = __half22float2(a.h);
    const float2 fb = __half22float2(b.h);
    return make_float4(fa.x, fa.y, fb.x, fb.y);
}

// ===========================================================================
// fp32 -> fp16 conversion of all six GEMM inputs, 4 float4 per thread (ILP).
// ===========================================================================
#define XN4 ((M_ * D_) / 4)   /* 2097152 */
#define WN4 ((D_ * D_) / 4)   /*  262144 */
#define CVT_TOTAL  (3 * XN4 + 3 * WN4)
#define CVT_QUADS  (CVT_TOTAL / 4)

__global__ __launch_bounds__(256)
void cvt_kernel(const float4* __restrict__ q, const float4* __restrict__ k,
                const float4* __restrict__ v, const float4* __restrict__ wq,
                const float4* __restrict__ wk, const float4* __restrict__ wv)
{
    const int qi = blockIdx.x * blockDim.x + threadIdx.x;
    if (qi >= CVT_QUADS) return;
    const int i = qi * 4;

    const float4* src;
    uint32_t* dstw;
    int off;
    if (i < 3 * XN4) {
        const int seg = i / XN4; off = i - seg * XN4;
        src = (seg == 0) ? q : (seg == 1) ? k : v;
        dstw = (uint32_t*)((seg == 0) ? g_qh : (seg == 1) ? g_kh : g_vh);
    } else {
        const int j = i - 3 * XN4;
        const int seg = j / WN4; off = j - seg * WN4;
        src = (seg == 0) ? wq : (seg == 1) ? wk : wv;
        dstw = (uint32_t*)((seg == 0) ? g_wqh : (seg == 1) ? g_wkh : g_wvh);
    }
    const float4 v0 = src[off];
    const float4 v1 = src[off + 1];
    const float4 v2 = src[off + 2];
    const float4 v3 = src[off + 3];
    uint4 o0, o1;
    o0.x = h2_bits(__floats2half2_rn(v0.x, v0.y));
    o0.y = h2_bits(__floats2half2_rn(v0.z, v0.w));
    o0.z = h2_bits(__floats2half2_rn(v1.x, v1.y));
    o0.w = h2_bits(__floats2half2_rn(v1.z, v1.w));
    o1.x = h2_bits(__floats2half2_rn(v2.x, v2.y));
    o1.y = h2_bits(__floats2half2_rn(v2.z, v2.w));
    o1.z = h2_bits(__floats2half2_rn(v3.x, v3.y));
    o1.w = h2_bits(__floats2half2_rn(v3.z, v3.w));
    *(uint4*)(dstw + off * 2)     = o0;
    *(uint4*)(dstw + off * 2 + 4) = o1;
}

// ===========================================================================
// Fused fp16 GEMM x3:  C[M,N] = X[M,K] @ W^T + bias  (blockIdx.z selects QKV)
// CTA tile 256x128, BK=64 halves, 512 threads / 16 warps (4m x 4n),
// warp tile 64x32. 3-stage cp.async pipeline (144 KB smem), ONE
// __syncthreads per iteration. K-GEMM skips the dead head-7 column tile.
// ===========================================================================
#define BKC     64
#define NITER   (D_ / BKC)               /* 16 */
#define BM_     256
#define A_TILE  (BM_ * 128)              /* 32 KB */
#define B_TILE  (128 * 128)              /* 16 KB */
#define STAGE_B (A_TILE + B_TILE)        /* 48 KB */
#define NSTAGE  3
#define SMEM_SZ (NSTAGE * STAGE_B)       /* 144 KB */

__global__ __launch_bounds__(512)
void gemm_f16_fused(const __half* __restrict__ X0, const __half* __restrict__ W0,
                    const float* __restrict__ b0, __half* __restrict__ C0,
                    const __half* __restrict__ X1, const __half* __restrict__ W1,
                    const float* __restrict__ b1, __half* __restrict__ C1,
                    const __half* __restrict__ X2, const __half* __restrict__ W2,
                    const float* __restrict__ b2, __half* __restrict__ C2)
{
    const int z = blockIdx.z;
    const int bx = blockIdx.x;
    if (z == 1 && bx == 7) return;   // k head 7 never read by attention

    const __half* X    = (z == 0) ? X0 : (z == 1) ? X1 : X2;
    const __half* W    = (z == 0) ? W0 : (z == 1) ? W1 : W2;
    const float*  bias = (z == 0) ? b0 : (z == 1) ? b1 : b2;
    __half*       C    = (z == 0) ? C0 : (z == 1) ? C1 : C2;

    extern __shared__ char smem[];
    const uint32_t sbase = smem_u32(smem);
    const int tid  = threadIdx.x;
    const int wid  = tid >> 5;
    const int lane = tid & 31;
    const int wm   = wid >> 2;          // 0..3
    const int wn   = wid & 3;           // 0..3

    const int bm = blockIdx.y * BM_;
    const int bn = bx * 128;
    const int K  = D_;

    float acc[4][4][4];
#pragma unroll
    for (int i = 0; i < 4; i++)
#pragma unroll
        for (int j = 0; j < 4; j++)
#pragma unroll
            for (int r = 0; r < 4; r++) acc[i][j][r] = 0.0f;

    auto load_stage = [&](int s, int k0) {
        const uint32_t sa = sbase + s * STAGE_B;
        const uint32_t sb = sa + A_TILE;
        const __half* Ab = X + (size_t)bm * K + k0 * BKC;
        const __half* Bb = W + (size_t)bn * K + k0 * BKC;
#pragma unroll
        for (int i = 0; i < 4; i++) {
            const int c   = i * 512 + tid;
            const int row = c >> 3;
            const int c16 = c & 7;
            const uint32_t off = SWZ128((uint32_t)(row * 128 + c16 * 16));
            cp_async16(sa + off, Ab + (size_t)row * K + c16 * 8);
        }
#pragma unroll
        for (int i = 0; i < 2; i++) {
            const int c   = i * 512 + tid;
            const int row = c >> 3;
            const int c16 = c & 7;
            const uint32_t off = SWZ128((uint32_t)(row * 128 + c16 * 16));
            cp_async16(sb + off, Bb + (size_t)row * K + c16 * 8);
        }
        CP_COMMIT();
    };

    load_stage(0, 0);
    load_stage(1, 1);

    const int a_row = wm * 64 + (lane & 15);
    const int a_byt = (lane >> 4) << 4;
    const int b_row = wn * 32 + ((lane >> 4) << 3) + (lane & 7);
    const int b_byt = ((lane >> 3) & 1) << 4;

    int cur = 0;
    for (int k0 = 0; k0 < NITER; k0++) {
        if (k0 < NITER - 1) { CP_WAIT(1); }
        else                { CP_WAIT(0); }
        __syncthreads();   // data visible + WAR on the slot issued below

        if (k0 + 2 < NITER)
            load_stage((cur + 2) % NSTAGE, k0 + 2);

        const uint32_t sa = sbase + cur * STAGE_B;
        const uint32_t sb = sa + A_TILE;

#pragma unroll
        for (int kk = 0; kk < 4; kk++) {
            const int kbyte = kk * 32;

            uint32_t af[4][4];
#pragma unroll
            for (int i = 0; i < 4; i++) {
                const uint32_t ad = sa + SWZ128((uint32_t)((a_row + i * 16) * 128
                                                           + kbyte + a_byt));
                ldsm_x4(af[i][0], af[i][1], af[i][2], af[i][3], ad);
            }
            uint32_t bf[4][2];
#pragma unroll
            for (int j2 = 0; j2 < 2; j2++) {
                const uint32_t bd = sb + SWZ128((uint32_t)((b_row + j2 * 16) * 128
                                                           + kbyte + b_byt));
                uint32_t r0, r1, r2, r3;
                ldsm_x4(r0, r1, r2, r3, bd);
                bf[j2 * 2][0] = r0; bf[j2 * 2][1] = r1;
                bf[j2 * 2 + 1][0] = r2; bf[j2 * 2 + 1][1] = r3;
            }
#pragma unroll
            for (int i = 0; i < 4; i++)
#pragma unroll
                for (int j = 0; j < 4; j++)
                    mma_f16(acc[i][j][0], acc[i][j][1], acc[i][j][2], acc[i][j][3],
                            af[i][0], af[i][1], af[i][2], af[i][3],
                            bf[j][0], bf[j][1]);
        }
        cur = (cur + 1) % NSTAGE;
    }

    const int lr = lane >> 2;
    const int lc = lane & 3;
#pragma unroll
    for (int i = 0; i < 4; i++) {
        const int row0 = bm + wm * 64 + i * 16 + lr;
#pragma unroll
        for (int j = 0; j < 4; j++) {
            const int col0 = bn + wn * 32 + j * 8 + lc * 2;
            const float bb0 = bias[col0], bb1 = bias[col0 + 1];
            const __half2 v0 = __floats2half2_rn(acc[i][j][0] + bb0, acc[i][j][1] + bb1);
            const __half2 v1 = __floats2half2_rn(acc[i][j][2] + bb0, acc[i][j][3] + bb1);
            *(__half2*)&C[(size_t)row0 * D_ + col0] = v0;
            *(__half2*)&C[(size_t)(row0 + 8) * D_ + col0] = v1;
        }
    }
}

// ---------------------------------------------------------------------------
// Attention: one warp per QUAD (ta, ta+d, ta+2d, ta+3d) of one (b, h).
// Window slot j of t_m reads shared source row i = j + m; the union is
// L+3 = 8 rows for 4 queries (2 rows/t vs 3/t for pairs). fp16 loads,
// fp32 math. Lane l handles dims [4l, 4l+4).
// ---------------------------------------------------------------------------
#define NQ 4
#define NROW (L_ + NQ - 1)   /* 8 */

__global__ __launch_bounds__(256)
void attn_kernel(const float* __restrict__ Er, const int* __restrict__ layer_p,
                 float* __restrict__ out, int write_attn)
{
    const int gwarp = (blockIdx.x * blockDim.x + threadIdx.x) >> 5;
    const int lane  = threadIdx.x & 31;
    const int nquad = T_ / NQ;
    if (gwarp >= B_ * H_ * nquad) return;

    const int p = gwarp % nquad;
    const int h = (gwarp / nquad) % H_;
    const int b = gwarp / (nquad * H_);

    const int layer = layer_p ? *layer_p : 1;
    const int dil = 1 << layer;
    const int pad = dil * (L_ / 2);
    const int Tp  = T_ + 2 * pad;

    // quad mapping: groups of NQ*dil positions -> (ta + m*dil), m = 0..3
    const int g  = p / dil, r = p % dil;
    const int ta = g * NQ * dil + r;

    const int srck[H_]   = {0, 1, 2, 3, 4, 5, 6, 6};
    const int shifts[H_] = {0, 0, 0, 0, -2, -1, 1, 2};
    const int sh = shifts[h];
    const int kcol = srck[h] * HD_;
    const int hcol = h * HD_;

    // q for the 4 queries
    float4 qv[NQ];
#pragma unroll
    for (int m = 0; m < NQ; m++) {
        const int tm = ta + m * dil;
        qv[m] = (tm < T_) ? ldh4(g_q + (size_t)(b * T_ + tm) * D_ + hcol + lane * 4)
                          : make_float4(0.f, 0.f, 0.f, 0.f);
    }

    // Er once for the quad
    float er[4][L_];
    const float* erp = Er + ((size_t)h * HD_ + lane * 4) * L_;
#pragma unroll
    for (int d = 0; d < 4; d++)
#pragma unroll
        for (int j = 0; j < L_; j++) er[d][j] = erp[d * L_ + j];

    // shared source rows: row i serves slot j = i - m of query m
    int  tt[NROW];
    bool val[NROW];
    float dk[NQ][L_];
#pragma unroll
    for (int i = 0; i < NROW; i++) {
        int pi = ta + (sh + i) * dil;
        pi %= Tp; if (pi < 0) pi += Tp;
        const bool v = (pi >= pad) && (pi < pad + T_);
        val[i] = v;
        tt[i] = pi - pad;

        float4 k4 = make_float4(0.f, 0.f, 0.f, 0.f);
        if (v)
            k4 = ldh4(g_k + (size_t)(b * T_ + tt[i]) * D_ + kcol + lane * 4);
#pragma unroll
        for (int m = 0; m < NQ; m++) {
            const int j = i - m;
            if (j >= 0 && j < L_)
                dk[m][j] = qv[m].x * k4.x + qv[m].y * k4.y
                         + qv[m].z * k4.z + qv[m].w * k4.w;
        }
    }

    // bias + 4-way interleaved butterfly reductions
    float s[NQ][L_];
#pragma unroll
    for (int j = 0; j < L_; j++) {
        float rr[NQ];
#pragma unroll
        for (int m = 0; m < NQ; m++)
            rr[m] = dk[m][j] + qv[m].x * er[0][j] + qv[m].y * er[1][j]
                             + qv[m].z * er[2][j] + qv[m].w * er[3][j];
#pragma unroll
        for (int o = 16; o > 0; o >>= 1) {
#pragma unroll
            for (int m = 0; m < NQ; m++)
                rr[m] += __shfl_xor_sync(0xffffffffu, rr[m], o);
        }
#pragma unroll
        for (int m = 0; m < NQ; m++)
            s[m][j] = val[j + m] ? (rr[m] * 0.08838834764831845f) : -INFINITY;
    }

    // softmax per query
    float w[NQ][L_], inv[NQ];
#pragma unroll
    for (int m = 0; m < NQ; m++) {
        float mx = s[m][0];
#pragma unroll
        for (int j = 1; j < L_; j++) mx = fmaxf(mx, s[m][j]);
        float sum = 0.f;
#pragma unroll
        for (int j = 0; j < L_; j++) { w[m][j] = expf(s[m][j] - mx); sum += w[m][j]; }
        inv[m] = 1.0f / sum;
    }

    // V accumulation over shared rows
    float4 o4[NQ];
#pragma unroll
    for (int m = 0; m < NQ; m++) o4[m] = make_float4(0.f, 0.f, 0.f, 0.f);
#pragma unroll
    for (int i = 0; i < NROW; i++) {
        if (val[i]) {
            const float4 v4 = ldh4(g_v + (size_t)(b * T_ + tt[i]) * D_
                                   + hcol + lane * 4);
#pragma unroll
            for (int m = 0; m < NQ; m++) {
                const int j = i - m;
                if (j >= 0 && j < L_) {
                    const float a = w[m][j] * inv[m];
                    o4[m].x = fmaf(a, v4.x, o4[m].x);
                    o4[m].y = fmaf(a, v4.y, o4[m].y);
                    o4[m].z = fmaf(a, v4.z, o4[m].z);
                    o4[m].w = fmaf(a, v4.w, o4[m].w);
                }
            }
        }
    }

#pragma unroll
    for (int m = 0; m < NQ; m++) {
        const int tm = ta + m * dil;
        if (tm < T_)
            *(float4*)(out + (size_t)(b * T_ + tm) * D_ + hcol + lane * 4) = o4[m];
    }

    if (write_attn && lane < L_) {
        const size_t base = (size_t)M_ * D_;
#pragma unroll
        for (int m = 0; m < NQ; m++) {
            const int tm = ta + m * dil;
            if (tm < T_)
                out[base + (((size_t)(b * H_ + h)) * T_ + tm) * L_ + lane]
                    = w[m][lane] * inv[m];
        }
    }
}

extern "C" void kernel_launch(void* const* d_in, const int* in_sizes, int n_in,
                              void* d_out, int out_size)
{
    const float* query = (const float*)d_in[0];
    const float* key   = (const float*)d_in[1];
    const float* value = (const float*)d_in[2];
    const float* Wq    = (const float*)d_in[3];
    const float* bq    = (const float*)d_in[4];
    const float* Wk    = (const float*)d_in[5];
    const float* bk    = (const float*)d_in[6];
    const float* Wv    = (const float*)d_in[7];
    const float* bv    = (const float*)d_in[8];
    const float* Er    = (const float*)d_in[9];
    const int*   layer = (n_in > 10) ? (const int*)d_in[10] : nullptr;

    __half *qo, *ko, *vo;
    cudaGetSymbolAddress((void**)&qo, g_q);
    cudaGetSymbolAddress((void**)&ko, g_k);
    cudaGetSymbolAddress((void**)&vo, g_v);
    __half *qh, *kh, *vh, *wqh, *wkh, *wvh;
    cudaGetSymbolAddress((void**)&qh, g_qh);
    cudaGetSymbolAddress((void**)&kh, g_kh);
    cudaGetSymbolAddress((void**)&vh, g_vh);
    cudaGetSymbolAddress((void**)&wqh, g_wqh);
    cudaGetSymbolAddress((void**)&wkh, g_wkh);
    cudaGetSymbolAddress((void**)&wvh, g_wvh);

    cvt_kernel<<<(CVT_QUADS + 255) / 256, 256>>>(
        (const float4*)query, (const float4*)key, (const float4*)value,
        (const float4*)Wq, (const float4*)Wk, (const float4*)Wv);

    cudaFuncSetAttribute(gemm_f16_fused,
                         cudaFuncAttributeMaxDynamicSharedMemorySize, SMEM_SZ);

    dim3 ggrid(D_ / 128, M_ / BM_, 3);   // (8, 32, 3)
    gemm_f16_fused<<<ggrid, 512, SMEM_SZ>>>(qh, wqh, bq, qo,
                                            kh, wkh, bk, ko,
                                            vh, wvh, bv, vo);

    const int write_attn = (out_size > M_ * D_) ? 1 : 0;
    const int total_warps = B_ * H_ * (T_ / NQ);
    attn_kernel<<<(total_warps * 32) / 256, 256>>>(Er, layer, (float*)d_out, write_attn);
}